// round 3
// baseline (speedup 1.0000x reference)
#include <cuda_runtime.h>
#include <cuda_bf16.h>

// UpProjectFastHadamardTransform: out[r, :] = FWHT_8192( scatter(u[r, :], idx) ) / sqrt(8192)
//
// Factorization of the 8192-pt WHT (all H2 tensor-factor stages commute):
//   bits 12:9 -> register dim (phase 1, 4 stages)
//   bits  4:0 -> lane dim     (phase 2, 5 shfl_xor stages)
//   bits  8:5 -> warp dim     (phase 3: one smem transpose puts them in the
//                              register dim, then 4 register stages)
// One CTA per row: 512 threads x 16 f32 regs = 8192 values resident.

#define D_DIM 8192
#define K_DIM 1024
#define NTHREADS 512
#define NREGS 16

__global__ __launch_bounds__(NTHREADS)
void fwht_up_kernel(const float* __restrict__ u,
                    const int*   __restrict__ idx,
                    float*       __restrict__ out)
{
    __shared__ float z[D_DIM];

    const int t = threadIdx.x;       // 9 bits
    const int l = t & 31;            // lane  -> output bits 4:0
    const int w = t >> 5;            // warp  -> (phase 3) output bits 12:9
    const int row = blockIdx.x;

    // ---- zero + scatter into smem ----
    float4* z4 = reinterpret_cast<float4*>(z);
    #pragma unroll
    for (int q = 0; q < (D_DIM / 4) / NTHREADS; q++)
        z4[t + q * NTHREADS] = make_float4(0.f, 0.f, 0.f, 0.f);
    __syncthreads();

    const float* urow = u + (size_t)row * K_DIM;
    #pragma unroll
    for (int q = 0; q < K_DIM / NTHREADS; q++) {
        int k = t + q * NTHREADS;
        atomicAdd(&z[idx[k]], urow[k]);
    }
    __syncthreads();

    // ---- phase 1: load strided, 4 butterfly stages over register index (bits 12:9) ----
    float r[NREGS];
    #pragma unroll
    for (int j = 0; j < NREGS; j++)
        r[j] = z[j * NTHREADS + t];          // addr mod 32 == l : conflict-free

    #pragma unroll
    for (int s = 1; s < NREGS; s <<= 1) {
        #pragma unroll
        for (int m = 0; m < NREGS; m++) {
            if ((m & s) == 0) {
                float a = r[m], b = r[m + s];
                r[m]     = a + b;
                r[m + s] = a - b;
            }
        }
    }

    // ---- phase 2: 5 shuffle stages over lane bits (bits 4:0) ----
    #pragma unroll
    for (int s = 1; s < 32; s <<= 1) {
        #pragma unroll
        for (int j = 0; j < NREGS; j++) {
            float o = __shfl_xor_sync(0xffffffffu, r[j], s);
            r[j] = (l & s) ? (o - r[j]) : (r[j] + o);
        }
    }

    // ---- phase 3: smem transpose so warp bits 8:5 land in the register dim ----
    __syncthreads();   // all phase-1 reads of z must complete before overwrite
    #pragma unroll
    for (int j = 0; j < NREGS; j++)
        z[j * NTHREADS + t] = r[j];
    __syncthreads();

    float r2[NREGS];
    #pragma unroll
    for (int j2 = 0; j2 < NREGS; j2++)
        r2[j2] = z[w * NTHREADS + j2 * 32 + l];   // addr mod 32 == l : conflict-free

    #pragma unroll
    for (int s = 1; s < NREGS; s <<= 1) {
        #pragma unroll
        for (int m = 0; m < NREGS; m++) {
            if ((m & s) == 0) {
                float a = r2[m], b = r2[m + s];
                r2[m]     = a + b;
                r2[m + s] = a - b;
            }
        }
    }

    // ---- epilogue: scaled, coalesced stores (128B per (w,j2) per warp) ----
    const float scale = 0.0110485434560398047f;   // 1/sqrt(8192)
    float* orow = out + (size_t)row * D_DIM;
    #pragma unroll
    for (int j2 = 0; j2 < NREGS; j2++)
        orow[w * NTHREADS + j2 * 32 + l] = r2[j2] * scale;
}

extern "C" void kernel_launch(void* const* d_in, const int* in_sizes, int n_in,
                              void* d_out, int out_size)
{
    const float* u   = (const float*)d_in[0];
    const int*   idx = (const int*)d_in[1];
    float*       out = (float*)d_out;

    const int rows = in_sizes[0] / K_DIM;   // 4*2048 = 8192
    fwht_up_kernel<<<rows, NTHREADS>>>(u, idx, out);
}

// round 5
// speedup vs baseline: 1.3774x; 1.3774x over previous
#include <cuda_runtime.h>
#include <cuda_bf16.h>

// UpProjectFastHadamardTransform: out[r,:] = FWHT_8192(scatter(u[r,:], idx)) / sqrt(8192)
//
// All 13 H2 tensor-factor stages commute, so assign address bits to resources:
//   phase A: bits 4:0  in registers (5 stages)   -- thread owns 32 contiguous values
//   phase B: bits 9:5  in registers (5 stages)   -- after smem transpose 1
//   phase C: bits 12:10 in registers (3 stages)  -- after smem transpose 2,
//            with bits 1:0 also in registers => float4 loads & stores
// Zero shuffles. Both transposes are bank-conflict-free (XOR swizzle on buffer 1,
// natural layout + vector access on buffer-2 pattern).
//
// One CTA per row: 256 threads x 32 f32 regs = 8192 values resident.

#define D_DIM 8192
#define K_DIM 1024
#define NTHREADS 256
#define NREGS 32

__device__ __forceinline__ int swz(int a) {
    // XOR address bits [4:2] with bits [7:5]; involution, bank-conflict killer
    return a ^ (((a >> 5) & 7) << 2);
}

__global__ __launch_bounds__(NTHREADS)
void fwht_up_kernel(const float* __restrict__ u,
                    const int*   __restrict__ idx,
                    float*       __restrict__ out)
{
    __shared__ float z[D_DIM];
    float4* z4 = reinterpret_cast<float4*>(z);

    const int t  = threadIdx.x;   // 8 bits
    const int l  = t & 31;        // lane
    const int h  = t >> 5;        // warp id (3 bits)
    const int row = blockIdx.x;

    // ---- zero smem (32 KB) ----
    #pragma unroll
    for (int q = 0; q < 8; q++)
        z4[t + q * NTHREADS] = make_float4(0.f, 0.f, 0.f, 0.f);
    __syncthreads();

    // ---- scatter: one float4/int4 per thread (K = 4*NTHREADS), smem atomics ----
    {
        const int4   i4 = reinterpret_cast<const int4*>(idx)[t];
        const float4 u4 = reinterpret_cast<const float4*>(u + (size_t)row * K_DIM)[t];
        atomicAdd(&z[swz(i4.x)], u4.x);
        atomicAdd(&z[swz(i4.y)], u4.y);
        atomicAdd(&z[swz(i4.z)], u4.z);
        atomicAdd(&z[swz(i4.w)], u4.w);
    }
    __syncthreads();

    float r[NREGS];

    // ---- R1: thread t loads its OWN logical range [t*32, t*32+32), swizzled float4.
    // physical granule = t*8 + (q ^ (t&7)); holds logical j = 4q..4q+3. Conflict-free.
    #pragma unroll
    for (int q = 0; q < 8; q++) {
        float4 v = z4[t * 8 + (q ^ (t & 7))];
        r[4*q + 0] = v.x; r[4*q + 1] = v.y; r[4*q + 2] = v.z; r[4*q + 3] = v.w;
    }

    // ---- phase A: 5 butterfly stages over bits 4:0 (register index) ----
    #pragma unroll
    for (int s = 1; s < 32; s <<= 1) {
        #pragma unroll
        for (int m = 0; m < NREGS; m++) {
            if ((m & s) == 0) {
                float a = r[m], b = r[m + s];
                r[m]     = a + b;
                r[m + s] = a - b;
            }
        }
    }

    // ---- W2: write back to own granules (no cross-thread hazard => no barrier yet) ----
    #pragma unroll
    for (int q = 0; q < 8; q++)
        z4[t * 8 + (q ^ (t & 7))] = make_float4(r[4*q], r[4*q+1], r[4*q+2], r[4*q+3]);
    __syncthreads();

    // ---- R2: new layout: reg = bits 9:5, lane = bits 4:0, warp = bits 12:10.
    // logical a = h*1024 + j2*32 + l ; physical low5 = l ^ ((j2&7)<<2). Conflict-free.
    #pragma unroll
    for (int j2 = 0; j2 < NREGS; j2++)
        r[j2] = z[h * 1024 + j2 * 32 + (l ^ ((j2 & 7) << 2))];

    // ---- phase B: 5 butterfly stages over bits 9:5 (register index) ----
    #pragma unroll
    for (int s = 1; s < 32; s <<= 1) {
        #pragma unroll
        for (int m = 0; m < NREGS; m++) {
            if ((m & s) == 0) {
                float a = r[m], b = r[m + s];
                r[m]     = a + b;
                r[m + s] = a - b;
            }
        }
    }
    __syncthreads();   // all R2 reads done before overwriting in natural layout

    // ---- W3: natural layout, stride-1 per warp instruction. Conflict-free. ----
    #pragma unroll
    for (int j2 = 0; j2 < NREGS; j2++)
        z[h * 1024 + j2 * 32 + l] = r[j2];
    __syncthreads();

    // ---- R3: reg = bits 12:10 (jh) and bits 1:0 (c); thread = bits 9:2.
    // float4 at logical jh*1024 + t*4 : 512B contiguous per warp. Conflict-free.
    #pragma unroll
    for (int jh = 0; jh < 8; jh++) {
        float4 v = z4[jh * 256 + t];
        r[4*jh + 0] = v.x; r[4*jh + 1] = v.y; r[4*jh + 2] = v.z; r[4*jh + 3] = v.w;
    }

    // ---- phase C: 3 butterfly stages over bits 12:10 (j index bits 4:2) ----
    #pragma unroll
    for (int s = 4; s < 32; s <<= 1) {
        #pragma unroll
        for (int m = 0; m < NREGS; m++) {
            if ((m & s) == 0) {
                float a = r[m], b = r[m + s];
                r[m]     = a + b;
                r[m + s] = a - b;
            }
        }
    }

    // ---- epilogue: scaled float4 stores, 512B contiguous per warp instruction ----
    const float scale = 0.0110485434560398047f;   // 1/sqrt(8192)
    float4* orow4 = reinterpret_cast<float4*>(out + (size_t)row * D_DIM);
    #pragma unroll
    for (int jh = 0; jh < 8; jh++) {
        float4 v;
        v.x = r[4*jh + 0] * scale;
        v.y = r[4*jh + 1] * scale;
        v.z = r[4*jh + 2] * scale;
        v.w = r[4*jh + 3] * scale;
        orow4[jh * 256 + t] = v;
    }
}

extern "C" void kernel_launch(void* const* d_in, const int* in_sizes, int n_in,
                              void* d_out, int out_size)
{
    const float* u   = (const float*)d_in[0];
    const int*   idx = (const int*)d_in[1];
    float*       out = (float*)d_out;

    const int rows = in_sizes[0] / K_DIM;   // 4*2048 = 8192
    fwht_up_kernel<<<rows, NTHREADS>>>(u, idx, out);
}

// round 6
// speedup vs baseline: 1.5706x; 1.1402x over previous
#include <cuda_runtime.h>
#include <cuda_fp16.h>

// out[r,:] = FWHT_8192(scatter(u[r,:], idx)) / sqrt(8192)
//
// Phase layout (H2 factors commute):
//   phase A: bits 4:0  (5 stages)  regs, packed f32x2 along bit0 for stages 4:1
//   phase B: bits 8:5  (4 stages)  regs, passenger bit 4 = f32x2 packing lane
//   phase C: bits 12:9 (4 stages)  regs, passenger bit 8 = f32x2 packing lane
// All smem traffic is fp16 (__half2), halving L1 bytes; arithmetic is f32.
// Transpose 1 packs half2 along bit4 (shared A<->B), transpose 2 along bit8
// (shared B<->C). Bank mappings chosen so every LDS/STS is conflict-free:
//   T1 cell: {b12:10,b8:5 | bank: b9,(b8:5^b3:0)}
//   T2 cell: {b12:9,b7:5  | bank: (b4^b9),b3:0}

#define D_DIM 8192
#define K_DIM 1024
#define NT    256
#define SCALE_F 0.0110485434560398047f  // 1/sqrt(8192)

__device__ __forceinline__ float2 fadd2(float2 a, float2 b) {
    float2 c;
    asm("add.rn.f32x2 %0, %1, %2;"
        : "=l"(reinterpret_cast<unsigned long long &>(c))
        : "l"(reinterpret_cast<const unsigned long long &>(a)),
          "l"(reinterpret_cast<const unsigned long long &>(b)));
    return c;
}
// a*b + c
__device__ __forceinline__ float2 ffma2(float2 a, float2 b, float2 c) {
    float2 d;
    asm("fma.rn.f32x2 %0, %1, %2, %3;"
        : "=l"(reinterpret_cast<unsigned long long &>(d))
        : "l"(reinterpret_cast<const unsigned long long &>(a)),
          "l"(reinterpret_cast<const unsigned long long &>(b)),
          "l"(reinterpret_cast<const unsigned long long &>(c)));
    return d;
}
__device__ __forceinline__ float2 fmul2(float2 a, float2 b) {
    float2 c;
    asm("mul.rn.f32x2 %0, %1, %2;"
        : "=l"(reinterpret_cast<unsigned long long &>(c))
        : "l"(reinterpret_cast<const unsigned long long &>(a)),
          "l"(reinterpret_cast<const unsigned long long &>(b)));
    return c;
}

__global__ __launch_bounds__(NT)
void fwht_up_kernel(const float* __restrict__ u,
                    const int*   __restrict__ idx,
                    float*       __restrict__ out)
{
    __shared__ __align__(16) __half2 zb[4096];   // scatter buffer (fp16)
    __shared__ __align__(16) __half2 tb[4096];   // transpose buffer (fp16)

    const int t   = threadIdx.x;    // 8 bits
    const int row = blockIdx.x;

    // ---- scatter-cell precompute (z layout: cell = t_v*16 + (q_v ^ swz)) ----
    const int4 iv = reinterpret_cast<const int4*>(idx)[t];
    int vs[4] = {iv.x, iv.y, iv.z, iv.w};
    int cell[4], comp[4];
#pragma unroll
    for (int j = 0; j < 4; j++) {
        int v  = vs[j];
        int tv = v >> 5;
        cell[j] = tv * 16 + (((v >> 1) & 15) ^ ((tv >> 1) & 15));
        comp[j] = v & 1;
    }

    // ---- zero zb (16KB, fp16) ----
    {
        float4* z4 = reinterpret_cast<float4*>(zb);
#pragma unroll
        for (int q = 0; q < 4; q++)
            z4[t + q * NT] = make_float4(0.f, 0.f, 0.f, 0.f);
    }
    __syncthreads();

    // ---- scatter: 4 native half2 atomics ----
    {
        const float4 u4 = reinterpret_cast<const float4*>(u + (size_t)row * K_DIM)[t];
        const float uv[4] = {u4.x, u4.y, u4.z, u4.w};
        const __half hz = __ushort_as_half((unsigned short)0);
#pragma unroll
        for (int j = 0; j < 4; j++) {
            __half h = __float2half_rn(uv[j]);
            __half2 hv = comp[j] ? __halves2half2(hz, h) : __halves2half2(h, hz);
            atomicAdd(&zb[cell[j]], hv);
        }
    }
    __syncthreads();

    // address constants
    const int s1   = (t >> 1) & 15;
    const int A2   = ((t >> 5) << 9) | ((t & 15) << 5) | (((t >> 4) & 1) << 4);
    const int A3   = ((t >> 5) << 9) | (((t >> 4) & 1) << 4);
    const int B2   = ((t >> 4) << 8) | (t & 15);
    const int selw = (t >> 4) & 1;
    const int B3   = ((t >> 5) << 5) | (t & 15);
    const float2 NEG1 = make_float2(-1.f, -1.f);

    float2 x[16];

    // ---- R1: thread t owns bits 12:5 = t; x[q] = pair over bit0 at bits4:1=q ----
#pragma unroll
    for (int q = 0; q < 16; q++)
        x[q] = __half22float2(zb[t * 16 + (q ^ s1)]);

    // ---- phase A: bits 4:1 packed, then bit0 scalar ----
#pragma unroll
    for (int s = 1; s < 16; s <<= 1)
#pragma unroll
        for (int i = 0; i < 16; i++)
            if ((i & s) == 0) {
                float2 a = x[i], b = x[i + s];
                x[i]     = fadd2(a, b);
                x[i + s] = ffma2(b, NEG1, a);
            }
#pragma unroll
    for (int i = 0; i < 16; i++) {
        float a = x[i].x, b = x[i].y;
        x[i].x = a + b;  x[i].y = a - b;
    }

    // ---- W2: pack half2 along bit4: (elem m, elem m+16) ----
#pragma unroll
    for (int m = 0; m < 16; m++) {
        float f0 = (m & 1) ? x[m >> 1].y       : x[m >> 1].x;
        float f1 = (m & 1) ? x[(m >> 1) + 8].y : x[(m >> 1) + 8].x;
        tb[A2 | ((t & 15) ^ m)] = __floats2half2_rn(f0, f1);
    }
    __syncthreads();

    // ---- R2: thread = {b12:9 = t>>4, b3:0 = t&15}; x[j] = pair over bit4 at bits8:5=j ----
#pragma unroll
    for (int j = 0; j < 16; j++)
        x[j] = __half22float2(tb[A3 | (j << 5) | (j ^ (t & 15))]);

    // ---- phase B: bits 8:5 packed (bit4 passenger) ----
#pragma unroll
    for (int s = 1; s < 16; s <<= 1)
#pragma unroll
        for (int i = 0; i < 16; i++)
            if ((i & s) == 0) {
                float2 a = x[i], b = x[i + s];
                x[i]     = fadd2(a, b);
                x[i + s] = ffma2(b, NEG1, a);
            }
    __syncthreads();   // all R2 reads done before tb overwrite

    // ---- W3: pack half2 along bit8: (j=jl, j=jl+8), component = bit4 ----
#pragma unroll
    for (int i2 = 0; i2 < 16; i2++) {
        int jl = i2 >> 1, c = i2 & 1;
        float f0 = c ? x[jl].y     : x[jl].x;
        float f1 = c ? x[jl + 8].y : x[jl + 8].x;
        tb[B2 | (jl << 5) | ((c ^ selw) << 4)] = __floats2half2_rn(f0, f1);
    }
    __syncthreads();

    // ---- R3: thread = bits 7:0; x[g] = pair over bit8 at bits12:9=g ----
#pragma unroll
    for (int g = 0; g < 16; g++)
        x[g] = __half22float2(tb[(g << 8) | B3 | ((selw ^ (g & 1)) << 4)]);

    // ---- phase C: bits 12:9 packed (bit8 passenger) ----
#pragma unroll
    for (int s = 1; s < 16; s <<= 1)
#pragma unroll
        for (int i = 0; i < 16; i++)
            if ((i & s) == 0) {
                float2 a = x[i], b = x[i + s];
                x[i]     = fadd2(a, b);
                x[i + s] = ffma2(b, NEG1, a);
            }

    // ---- scale + coalesced stores: a = g<<9 | comp<<8 | t ----
    const float2 SC2 = make_float2(SCALE_F, SCALE_F);
    float* orow = out + (size_t)row * D_DIM;
#pragma unroll
    for (int g = 0; g < 16; g++) {
        float2 v = fmul2(x[g], SC2);
        orow[(g << 9) | t]       = v.x;
        orow[(g << 9) | 256 | t] = v.y;
    }
}

extern "C" void kernel_launch(void* const* d_in, const int* in_sizes, int n_in,
                              void* d_out, int out_size)
{
    const float* u   = (const float*)d_in[0];
    const int*   idx = (const int*)d_in[1];
    float*       out = (float*)d_out;

    const int rows = in_sizes[0] / K_DIM;   // 8192
    fwht_up_kernel<<<rows, NT>>>(u, idx, out);
}